// round 14
// baseline (speedup 1.0000x reference)
#include <cuda_runtime.h>
#include <cuda_bf16.h>
#include <cuda_fp16.h>
#include <cstdint>

#define NMAX 50000
#define EMAX 800000
#define INDIM 128
#define ODIM 128

// ---- device scratch (no cudaMalloc allowed) ----
__device__ float  g_Q[NMAX * ODIM];            // Q[n][128] fp32
// per node 512B: 32 chunks of 16B; chunk l = {K[4l..4l+3] | V[4l..4l+3]} fp16
__device__ __half g_KVh[NMAX * 2 * ODIM];
__device__ unsigned char g_WThi[3][34816];     // W^T bf16 hi, padded stride 272B
__device__ unsigned char g_WTlo[3][34816];     // W^T bf16 lo
__device__ int   g_cnt[NMAX + 1];              // BSS-zero; re-zeroed by scan_partial
__device__ int   g_row[NMAX + 1];
__device__ int   g_rank[EMAX];                 // per-edge rank within dst bucket
__device__ int   g_srcs[EMAX];
__device__ int   g_bsum[64];

// ============================================================
// helpers
// ============================================================
__device__ __forceinline__ uint32_t smem_u32(const void* p) {
    uint32_t a;
    asm("{ .reg .u64 t; cvta.to.shared.u64 t, %1; cvt.u32.u64 %0, t; }" : "=r"(a) : "l"(p));
    return a;
}
__device__ __forceinline__ void ldm_x4(uint32_t& r0, uint32_t& r1, uint32_t& r2,
                                       uint32_t& r3, uint32_t addr) {
    asm volatile("ldmatrix.sync.aligned.m8n8.x4.shared.b16 {%0,%1,%2,%3}, [%4];"
                 : "=r"(r0), "=r"(r1), "=r"(r2), "=r"(r3) : "r"(addr));
}
__device__ __forceinline__ void mma_bf16(float& c0, float& c1, float& c2, float& c3,
                                         uint32_t a0, uint32_t a1, uint32_t a2, uint32_t a3,
                                         uint32_t b0, uint32_t b1) {
    asm volatile("mma.sync.aligned.m16n8k16.row.col.f32.bf16.bf16.f32 "
                 "{%0,%1,%2,%3}, {%4,%5,%6,%7}, {%8,%9}, {%0,%1,%2,%3};"
                 : "+f"(c0), "+f"(c1), "+f"(c2), "+f"(c3)
                 : "r"(a0), "r"(a1), "r"(a2), "r"(a3), "r"(b0), "r"(b1));
}

// smem tile layout: row stride 136 bf16 = 272 B
#define TSTRIDE 272
#define A_HI 0
#define A_LO 34816
#define B_HI 69632
#define B_LO 104448
#define SM_TOTAL 139264

// ============================================================
// W^T conversion to bf16 hi/lo: one warp per output row (R13 form).
// ============================================================
__global__ void conv_W(const float* __restrict__ WQ, const float* __restrict__ WK,
                       const float* __restrict__ WV) {
    int w = blockIdx.x * 8 + (threadIdx.x >> 5);
    int lane = threadIdx.x & 31;
    int m = w >> 7, n = w & 127;
    const float* W = (m == 0) ? WQ : (m == 1) ? WK : WV;

    int k0 = lane * 4;
    float x0 = W[(k0 + 0) * 128 + n];
    float x1 = W[(k0 + 1) * 128 + n];
    float x2 = W[(k0 + 2) * 128 + n];
    float x3 = W[(k0 + 3) * 128 + n];

    __nv_bfloat16 a0 = __float2bfloat16(x0);
    __nv_bfloat16 a1 = __float2bfloat16(x1);
    __nv_bfloat16 a2 = __float2bfloat16(x2);
    __nv_bfloat16 a3 = __float2bfloat16(x3);
    __nv_bfloat16 l0 = __float2bfloat16(x0 - __bfloat162float(a0));
    __nv_bfloat16 l1 = __float2bfloat16(x1 - __bfloat162float(a1));
    __nv_bfloat16 l2 = __float2bfloat16(x2 - __bfloat162float(a2));
    __nv_bfloat16 l3 = __float2bfloat16(x3 - __bfloat162float(a3));

    uint32_t hw0 = (uint32_t)__bfloat16_as_ushort(a0) | ((uint32_t)__bfloat16_as_ushort(a1) << 16);
    uint32_t hw1 = (uint32_t)__bfloat16_as_ushort(a2) | ((uint32_t)__bfloat16_as_ushort(a3) << 16);
    uint32_t lw0 = (uint32_t)__bfloat16_as_ushort(l0) | ((uint32_t)__bfloat16_as_ushort(l1) << 16);
    uint32_t lw1 = (uint32_t)__bfloat16_as_ushort(l2) | ((uint32_t)__bfloat16_as_ushort(l3) << 16);

    *reinterpret_cast<uint2*>(g_WThi[m] + n * TSTRIDE + k0 * 2) = make_uint2(hw0, hw1);
    *reinterpret_cast<uint2*>(g_WTlo[m] + n * TSTRIDE + k0 * 2) = make_uint2(lw0, lw1);
}

// ============================================================
// QKV GEMM (R7 form — proven): one CTA per tile, loops m = Q,K,V.
// ============================================================
__global__ void __launch_bounds__(256, 1)
qkv_hmma(const float* __restrict__ h,
         const float* __restrict__ bQ, const float* __restrict__ bK,
         const float* __restrict__ bV, int N) {
    extern __shared__ char smem[];
    uint32_t sb = smem_u32(smem);
    int tid = threadIdx.x;
    int t = blockIdx.x;

    // ---- convert h tile [128 x 128] -> A_hi/A_lo (once) ----
    {
        int r = tid >> 1, half = tid & 1;
        int node = t * 128 + r;
        const float4* hp = reinterpret_cast<const float4*>(h + (size_t)node * 128);
#pragma unroll
        for (int i = 0; i < 16; i++) {
            int c = half * 64 + i * 4;
            float4 x = make_float4(0.f, 0.f, 0.f, 0.f);
            if (node < N) x = hp[c >> 2];
            uint32_t ua = __float_as_uint(x.x), ub = __float_as_uint(x.y);
            uint32_t uc = __float_as_uint(x.z), ud = __float_as_uint(x.w);
            uint32_t h0 = __byte_perm(ua, ub, 0x7632);
            uint32_t h1 = __byte_perm(uc, ud, 0x7632);
            float la = x.x - __uint_as_float(ua & 0xFFFF0000u);
            float lb = x.y - __uint_as_float(ub & 0xFFFF0000u);
            float lc = x.z - __uint_as_float(uc & 0xFFFF0000u);
            float ld = x.w - __uint_as_float(ud & 0xFFFF0000u);
            uint32_t l0, l1;
            asm("cvt.rn.bf16x2.f32 %0, %1, %2;" : "=r"(l0) : "f"(lb), "f"(la));
            asm("cvt.rn.bf16x2.f32 %0, %1, %2;" : "=r"(l1) : "f"(ld), "f"(lc));
            *reinterpret_cast<uint2*>(smem + A_HI + r * TSTRIDE + c * 2) = make_uint2(h0, h1);
            *reinterpret_cast<uint2*>(smem + A_LO + r * TSTRIDE + c * 2) = make_uint2(l0, l1);
        }
    }

    int wid = tid >> 5, lane = tid & 31;
    int wm = wid & 3, wn = wid >> 2;
    uint32_t aRel = (uint32_t)((wm * 32 + (lane & 15)) * TSTRIDE + (lane >> 4) * 16);
    uint32_t bRel = (uint32_t)((wn * 64 + (lane & 7) + ((lane >> 4) << 3)) * TSTRIDE +
                               (((lane >> 3) & 1) << 4));

    for (int m = 0; m < 3; m++) {
        {
            const uint4* sH = reinterpret_cast<const uint4*>(g_WThi[m]);
            const uint4* sL = reinterpret_cast<const uint4*>(g_WTlo[m]);
            uint4* dH = reinterpret_cast<uint4*>(smem + B_HI);
            uint4* dL = reinterpret_cast<uint4*>(smem + B_LO);
            for (int i = tid; i < 2176; i += 256) {
                dH[i] = sH[i];
                dL[i] = sL[i];
            }
        }
        __syncthreads();

        float acc[2][8][4];
#pragma unroll
        for (int mt = 0; mt < 2; mt++)
#pragma unroll
            for (int nt = 0; nt < 8; nt++)
#pragma unroll
                for (int q = 0; q < 4; q++) acc[mt][nt][q] = 0.f;

#pragma unroll
        for (int term = 0; term < 3; term++) {
            uint32_t aBase = sb + ((term == 1) ? A_LO : A_HI) + aRel;
            uint32_t bBase = sb + ((term == 2) ? B_LO : B_HI) + bRel;
#pragma unroll
            for (int k16 = 0; k16 < 8; k16++) {
                uint32_t af[2][4];
                ldm_x4(af[0][0], af[0][1], af[0][2], af[0][3], aBase + k16 * 32);
                ldm_x4(af[1][0], af[1][1], af[1][2], af[1][3], aBase + 16 * TSTRIDE + k16 * 32);
                uint32_t bf[4][4];
#pragma unroll
                for (int nb = 0; nb < 4; nb++)
                    ldm_x4(bf[nb][0], bf[nb][1], bf[nb][2], bf[nb][3],
                           bBase + nb * 16 * TSTRIDE + k16 * 32);
#pragma unroll
                for (int mt = 0; mt < 2; mt++)
#pragma unroll
                    for (int nb = 0; nb < 4; nb++) {
                        mma_bf16(acc[mt][nb * 2][0], acc[mt][nb * 2][1],
                                 acc[mt][nb * 2][2], acc[mt][nb * 2][3],
                                 af[mt][0], af[mt][1], af[mt][2], af[mt][3],
                                 bf[nb][0], bf[nb][1]);
                        mma_bf16(acc[mt][nb * 2 + 1][0], acc[mt][nb * 2 + 1][1],
                                 acc[mt][nb * 2 + 1][2], acc[mt][nb * 2 + 1][3],
                                 af[mt][0], af[mt][1], af[mt][2], af[mt][3],
                                 bf[nb][2], bf[nb][3]);
                    }
            }
        }

        // ---- epilogue: Q fp32; K/V fp16 interleaved chunks ----
        const float* bias = (m == 0) ? bQ : (m == 1) ? bK : bV;
        char* kvb = reinterpret_cast<char*>(g_KVh);
#pragma unroll
        for (int nt = 0; nt < 8; nt++) {
            int col = wn * 64 + nt * 8 + (lane & 3) * 2;
            float b0 = bias[col], b1 = bias[col + 1];
#pragma unroll
            for (int mt = 0; mt < 2; mt++) {
                int row = t * 128 + wm * 32 + mt * 16 + (lane >> 2);
#pragma unroll
                for (int half = 0; half < 2; half++) {
                    int rr = row + half * 8;
                    if (rr >= N) continue;
                    float v0 = acc[mt][nt][2 * half] + b0;
                    float v1 = acc[mt][nt][2 * half + 1] + b1;
                    if (m == 0) {
                        *reinterpret_cast<float2*>(g_Q + (size_t)rr * 128 + col) =
                            make_float2(v0, v1);
                    } else {
                        __half2* o = reinterpret_cast<__half2*>(
                            kvb + (size_t)rr * 512 + (col >> 2) * 16 +
                            (m == 2 ? 8 : 0) + (col & 3) * 2);
                        *o = __floats2half2_rn(v0, v1);
                    }
                }
            }
        }
        __syncthreads();
    }
}

// ============================================================
// CSR construction (R10/R13 form — proven)
// ============================================================
__global__ void hist_k(const int* __restrict__ dst, int E) {
    int i = blockIdx.x * 256 + threadIdx.x;
    int base = i * 8;
    if (base + 7 < E) {
        int4 d0 = *reinterpret_cast<const int4*>(dst + base);
        int4 d1 = *reinterpret_cast<const int4*>(dst + base + 4);
        int r0 = atomicAdd(&g_cnt[d0.x], 1);
        int r1 = atomicAdd(&g_cnt[d0.y], 1);
        int r2 = atomicAdd(&g_cnt[d0.z], 1);
        int r3 = atomicAdd(&g_cnt[d0.w], 1);
        int r4 = atomicAdd(&g_cnt[d1.x], 1);
        int r5 = atomicAdd(&g_cnt[d1.y], 1);
        int r6 = atomicAdd(&g_cnt[d1.z], 1);
        int r7 = atomicAdd(&g_cnt[d1.w], 1);
        *reinterpret_cast<int4*>(g_rank + base)     = make_int4(r0, r1, r2, r3);
        *reinterpret_cast<int4*>(g_rank + base + 4) = make_int4(r4, r5, r6, r7);
    } else {
        for (int j = base; j < E; j++) g_rank[j] = atomicAdd(&g_cnt[dst[j]], 1);
    }
}

__device__ __forceinline__ int warp_incl_scan(int v, int lane) {
#pragma unroll
    for (int off = 1; off < 32; off <<= 1) {
        int t = __shfl_up_sync(0xffffffffu, v, off);
        if (lane >= off) v += t;
    }
    return v;
}

__global__ void scan_partial(int N) {
    __shared__ int wsum[32];
    int tid = threadIdx.x, lane = tid & 31, wid = tid >> 5;
    int idx = blockIdx.x * 1024 + tid;
    int x = 0;
    if (idx < N) {
        x = g_cnt[idx];
        g_cnt[idx] = 0;
    }
    int v = warp_incl_scan(x, lane);
    if (lane == 31) wsum[wid] = v;
    __syncthreads();
    if (wid == 0) wsum[lane] = warp_incl_scan(wsum[lane], lane);
    __syncthreads();
    int incl = v + (wid > 0 ? wsum[wid - 1] : 0);
    if (idx < N) g_row[idx] = incl - x;
    if (tid == 1023) g_bsum[blockIdx.x] = incl;
}

__global__ void scan_add(int N, int E) {
    __shared__ int boff;
    int b = blockIdx.x, tid = threadIdx.x;
    if (tid < 32) {
        int acc = 0;
        for (int i = tid; i < b; i += 32) acc += g_bsum[i];
#pragma unroll
        for (int o = 16; o; o >>= 1) acc += __shfl_xor_sync(0xffffffffu, acc, o);
        if (tid == 0) boff = acc;
    }
    __syncthreads();
    int idx = b * 1024 + tid;
    if (idx < N) g_row[idx] += boff;
    if (idx == 0) g_row[N] = E;
}

__global__ void scatter_k(const int* __restrict__ src, const int* __restrict__ dst, int E) {
    int i = blockIdx.x * 256 + threadIdx.x;
    int base = i * 8;
    if (base + 7 < E) {
        int4 s0 = *reinterpret_cast<const int4*>(src + base);
        int4 s1 = *reinterpret_cast<const int4*>(src + base + 4);
        int4 d0 = *reinterpret_cast<const int4*>(dst + base);
        int4 d1 = *reinterpret_cast<const int4*>(dst + base + 4);
        int4 r0 = *reinterpret_cast<const int4*>(g_rank + base);
        int4 r1 = *reinterpret_cast<const int4*>(g_rank + base + 4);
        g_srcs[g_row[d0.x] + r0.x] = s0.x;
        g_srcs[g_row[d0.y] + r0.y] = s0.y;
        g_srcs[g_row[d0.z] + r0.z] = s0.z;
        g_srcs[g_row[d0.w] + r0.w] = s0.w;
        g_srcs[g_row[d1.x] + r1.x] = s1.x;
        g_srcs[g_row[d1.y] + r1.y] = s1.y;
        g_srcs[g_row[d1.z] + r1.z] = s1.z;
        g_srcs[g_row[d1.w] + r1.w] = s1.w;
    } else {
        for (int j = base; j < E; j++)
            g_srcs[g_row[dst[j]] + g_rank[j]] = src[j];
    }
}

// ============================================================
// Gather attention: one warp per dst node, interleaved fp16 KV.
// Branchless software pipeline: prefetch next 4-edge batch with
// clamped indices (warp-uniform guard), tail validity via 0/1
// mask multiply (no per-lane predication on loads or compute).
// ============================================================
__global__ void gather_attn(float* __restrict__ out, int N) {
    int w = (blockIdx.x * blockDim.x + threadIdx.x) >> 5;
    int lane = threadIdx.x & 31;
    if (w >= N) return;

    const float4 q = reinterpret_cast<const float4*>(g_Q)[(size_t)w * 32 + lane];
    int beg = g_row[w], end = g_row[w + 1];

    float ax = 0.f, ay = 0.f, az = 0.f, aw = 0.f, z = 0.f;
    const uint4* KV = reinterpret_cast<const uint4*>(g_KVh);

    if (beg < end) {
        int last = end - 1;
        uint4 kvA[4];
#pragma unroll
        for (int j = 0; j < 4; j++) {
            int id = beg + j;
            id = id > last ? last : id;
            kvA[j] = KV[(size_t)g_srcs[id] * 32 + lane];
        }

        for (int base = beg; base < end; base += 4) {
            bool more = (base + 4) < end;        // warp-uniform
            uint4 kvB[4];
            if (more) {
#pragma unroll
                for (int j = 0; j < 4; j++) {
                    int id = base + 4 + j;
                    id = id > last ? last : id;
                    kvB[j] = KV[(size_t)g_srcs[id] * 32 + lane];
                }
            }
#pragma unroll
            for (int j = 0; j < 4; j++) {
                float valid = (base + j <= last) ? 1.f : 0.f;
                float2 ka = __half22float2(*reinterpret_cast<__half2*>(&kvA[j].x));
                float2 kb = __half22float2(*reinterpret_cast<__half2*>(&kvA[j].y));
                float d = ka.x * q.x + ka.y * q.y + kb.x * q.z + kb.y * q.w;
                d += __shfl_xor_sync(0xffffffffu, d, 1);
                d += __shfl_xor_sync(0xffffffffu, d, 2);
                float e = __expf(fminf(5.f, fmaxf(-5.f, d * 0.25f))) * valid;
                float2 va = __half22float2(*reinterpret_cast<__half2*>(&kvA[j].z));
                float2 vb = __half22float2(*reinterpret_cast<__half2*>(&kvA[j].w));
                z  += e;
                ax += va.x * e;
                ay += va.y * e;
                az += vb.x * e;
                aw += vb.y * e;
            }
            if (more) {
#pragma unroll
                for (int j = 0; j < 4; j++) kvA[j] = kvB[j];
            }
        }
    }

    float inv = (z > 0.f) ? 1.f / z : 0.f;
    reinterpret_cast<float4*>(out)[(size_t)w * 32 + lane] =
        make_float4(ax * inv, ay * inv, az * inv, aw * inv);
}

// ============================================================
extern "C" void kernel_launch(void* const* d_in, const int* in_sizes, int n_in,
                              void* d_out, int out_size) {
    const float* h  = (const float*)d_in[0];
    const int*   src = (const int*)d_in[1];
    const int*   dst = (const int*)d_in[2];
    const float* WQ = (const float*)d_in[3];
    const float* bQ = (const float*)d_in[4];
    const float* WK = (const float*)d_in[5];
    const float* bK = (const float*)d_in[6];
    const float* WV = (const float*)d_in[7];
    const float* bV = (const float*)d_in[8];
    int N = in_sizes[0] / INDIM;
    int E = in_sizes[1];
    int NT = (N + 127) / 128;

    cudaFuncSetAttribute(qkv_hmma, cudaFuncAttributeMaxDynamicSharedMemorySize, SM_TOTAL);

    cudaStream_t s2;
    cudaStreamCreateWithFlags(&s2, cudaStreamNonBlocking);
    cudaEvent_t evF, evJ;
    cudaEventCreateWithFlags(&evF, cudaEventDisableTiming);
    cudaEventCreateWithFlags(&evJ, cudaEventDisableTiming);

    cudaEventRecord(evF, 0);
    cudaStreamWaitEvent(s2, evF, 0);

    // --- s2: CSR chain (4 kernels, scatter atomic-free) ---
    int E8 = (E + 7) / 8;
    int nb = (N + 1023) / 1024;
    hist_k<<<(E8 + 255) / 256, 256, 0, s2>>>(dst, E);
    scan_partial<<<nb, 1024, 0, s2>>>(N);
    scan_add<<<nb, 1024, 0, s2>>>(N, E);
    scatter_k<<<(E8 + 255) / 256, 256, 0, s2>>>(src, dst, E);
    cudaEventRecord(evJ, s2);

    // --- default stream: QKV chain ---
    conv_W<<<48, 256>>>(WQ, WK, WV);
    qkv_hmma<<<NT, 256, SM_TOTAL>>>(h, bQ, bK, bV, N);

    cudaStreamWaitEvent(0, evJ, 0);
    gather_attn<<<(N + 7) / 8, 256>>>((float*)d_out, N);
}

// round 15
// speedup vs baseline: 1.1243x; 1.1243x over previous
#include <cuda_runtime.h>
#include <cuda_bf16.h>
#include <cuda_fp16.h>
#include <cstdint>

#define NMAX 50000
#define EMAX 800000
#define INDIM 128
#define ODIM 128

// ---- device scratch (no cudaMalloc allowed) ----
__device__ float  g_Q[NMAX * ODIM];            // Q[n][128] fp32
// per node 512B: 32 chunks of 16B; chunk l = {K[4l..4l+3] | V[4l..4l+3]} fp16
__device__ __half g_KVh[NMAX * 2 * ODIM];
__device__ unsigned char g_WThi[3][34816];     // W^T bf16 hi, padded stride 272B
__device__ unsigned char g_WTlo[3][34816];     // W^T bf16 lo
__device__ int   g_cnt[NMAX + 1];              // BSS-zero; re-zeroed by scan_partial
__device__ int   g_row[NMAX + 1];
__device__ int   g_rank[EMAX];                 // per-edge rank within dst bucket
__device__ int   g_srcs[EMAX];
__device__ int   g_bsum[64];

// ============================================================
// helpers
// ============================================================
__device__ __forceinline__ uint32_t smem_u32(const void* p) {
    uint32_t a;
    asm("{ .reg .u64 t; cvta.to.shared.u64 t, %1; cvt.u32.u64 %0, t; }" : "=r"(a) : "l"(p));
    return a;
}
__device__ __forceinline__ void ldm_x4(uint32_t& r0, uint32_t& r1, uint32_t& r2,
                                       uint32_t& r3, uint32_t addr) {
    asm volatile("ldmatrix.sync.aligned.m8n8.x4.shared.b16 {%0,%1,%2,%3}, [%4];"
                 : "=r"(r0), "=r"(r1), "=r"(r2), "=r"(r3) : "r"(addr));
}
__device__ __forceinline__ void mma_bf16(float& c0, float& c1, float& c2, float& c3,
                                         uint32_t a0, uint32_t a1, uint32_t a2, uint32_t a3,
                                         uint32_t b0, uint32_t b1) {
    asm volatile("mma.sync.aligned.m16n8k16.row.col.f32.bf16.bf16.f32 "
                 "{%0,%1,%2,%3}, {%4,%5,%6,%7}, {%8,%9}, {%0,%1,%2,%3};"
                 : "+f"(c0), "+f"(c1), "+f"(c2), "+f"(c3)
                 : "r"(a0), "r"(a1), "r"(a2), "r"(a3), "r"(b0), "r"(b1));
}

// smem tile layout: row stride 136 bf16 = 272 B
#define TSTRIDE 272
#define A_HI 0
#define A_LO 34816
#define B_HI 69632
#define B_LO 104448
#define SM_TOTAL 139264

// ============================================================
// W^T conversion to bf16 hi/lo: one warp per output row.
// 48 CTAs x 8 warps = 384 warps = 3 matrices x 128 n-rows.
// ============================================================
__global__ void conv_W(const float* __restrict__ WQ, const float* __restrict__ WK,
                       const float* __restrict__ WV) {
    int w = blockIdx.x * 8 + (threadIdx.x >> 5);
    int lane = threadIdx.x & 31;
    int m = w >> 7, n = w & 127;
    const float* W = (m == 0) ? WQ : (m == 1) ? WK : WV;

    int k0 = lane * 4;
    float x0 = W[(k0 + 0) * 128 + n];
    float x1 = W[(k0 + 1) * 128 + n];
    float x2 = W[(k0 + 2) * 128 + n];
    float x3 = W[(k0 + 3) * 128 + n];

    __nv_bfloat16 a0 = __float2bfloat16(x0);
    __nv_bfloat16 a1 = __float2bfloat16(x1);
    __nv_bfloat16 a2 = __float2bfloat16(x2);
    __nv_bfloat16 a3 = __float2bfloat16(x3);
    __nv_bfloat16 l0 = __float2bfloat16(x0 - __bfloat162float(a0));
    __nv_bfloat16 l1 = __float2bfloat16(x1 - __bfloat162float(a1));
    __nv_bfloat16 l2 = __float2bfloat16(x2 - __bfloat162float(a2));
    __nv_bfloat16 l3 = __float2bfloat16(x3 - __bfloat162float(a3));

    uint32_t hw0 = (uint32_t)__bfloat16_as_ushort(a0) | ((uint32_t)__bfloat16_as_ushort(a1) << 16);
    uint32_t hw1 = (uint32_t)__bfloat16_as_ushort(a2) | ((uint32_t)__bfloat16_as_ushort(a3) << 16);
    uint32_t lw0 = (uint32_t)__bfloat16_as_ushort(l0) | ((uint32_t)__bfloat16_as_ushort(l1) << 16);
    uint32_t lw1 = (uint32_t)__bfloat16_as_ushort(l2) | ((uint32_t)__bfloat16_as_ushort(l3) << 16);

    *reinterpret_cast<uint2*>(g_WThi[m] + n * TSTRIDE + k0 * 2) = make_uint2(hw0, hw1);
    *reinterpret_cast<uint2*>(g_WTlo[m] + n * TSTRIDE + k0 * 2) = make_uint2(lw0, lw1);
}

// ============================================================
// QKV GEMM (R7 form — proven): one CTA per tile, loops m = Q,K,V.
// ============================================================
__global__ void __launch_bounds__(256, 1)
qkv_hmma(const float* __restrict__ h,
         const float* __restrict__ bQ, const float* __restrict__ bK,
         const float* __restrict__ bV, int N) {
    extern __shared__ char smem[];
    uint32_t sb = smem_u32(smem);
    int tid = threadIdx.x;
    int t = blockIdx.x;

    // ---- convert h tile [128 x 128] -> A_hi/A_lo (once) ----
    {
        int r = tid >> 1, half = tid & 1;
        int node = t * 128 + r;
        const float4* hp = reinterpret_cast<const float4*>(h + (size_t)node * 128);
#pragma unroll
        for (int i = 0; i < 16; i++) {
            int c = half * 64 + i * 4;
            float4 x = make_float4(0.f, 0.f, 0.f, 0.f);
            if (node < N) x = hp[c >> 2];
            uint32_t ua = __float_as_uint(x.x), ub = __float_as_uint(x.y);
            uint32_t uc = __float_as_uint(x.z), ud = __float_as_uint(x.w);
            uint32_t h0 = __byte_perm(ua, ub, 0x7632);
            uint32_t h1 = __byte_perm(uc, ud, 0x7632);
            float la = x.x - __uint_as_float(ua & 0xFFFF0000u);
            float lb = x.y - __uint_as_float(ub & 0xFFFF0000u);
            float lc = x.z - __uint_as_float(uc & 0xFFFF0000u);
            float ld = x.w - __uint_as_float(ud & 0xFFFF0000u);
            uint32_t l0, l1;
            asm("cvt.rn.bf16x2.f32 %0, %1, %2;" : "=r"(l0) : "f"(lb), "f"(la));
            asm("cvt.rn.bf16x2.f32 %0, %1, %2;" : "=r"(l1) : "f"(ld), "f"(lc));
            *reinterpret_cast<uint2*>(smem + A_HI + r * TSTRIDE + c * 2) = make_uint2(h0, h1);
            *reinterpret_cast<uint2*>(smem + A_LO + r * TSTRIDE + c * 2) = make_uint2(l0, l1);
        }
    }

    int wid = tid >> 5, lane = tid & 31;
    int wm = wid & 3, wn = wid >> 2;
    uint32_t aRel = (uint32_t)((wm * 32 + (lane & 15)) * TSTRIDE + (lane >> 4) * 16);
    uint32_t bRel = (uint32_t)((wn * 64 + (lane & 7) + ((lane >> 4) << 3)) * TSTRIDE +
                               (((lane >> 3) & 1) << 4));

    for (int m = 0; m < 3; m++) {
        {
            const uint4* sH = reinterpret_cast<const uint4*>(g_WThi[m]);
            const uint4* sL = reinterpret_cast<const uint4*>(g_WTlo[m]);
            uint4* dH = reinterpret_cast<uint4*>(smem + B_HI);
            uint4* dL = reinterpret_cast<uint4*>(smem + B_LO);
            for (int i = tid; i < 2176; i += 256) {
                dH[i] = sH[i];
                dL[i] = sL[i];
            }
        }
        __syncthreads();

        float acc[2][8][4];
#pragma unroll
        for (int mt = 0; mt < 2; mt++)
#pragma unroll
            for (int nt = 0; nt < 8; nt++)
#pragma unroll
                for (int q = 0; q < 4; q++) acc[mt][nt][q] = 0.f;

#pragma unroll
        for (int term = 0; term < 3; term++) {
            uint32_t aBase = sb + ((term == 1) ? A_LO : A_HI) + aRel;
            uint32_t bBase = sb + ((term == 2) ? B_LO : B_HI) + bRel;
#pragma unroll
            for (int k16 = 0; k16 < 8; k16++) {
                uint32_t af[2][4];
                ldm_x4(af[0][0], af[0][1], af[0][2], af[0][3], aBase + k16 * 32);
                ldm_x4(af[1][0], af[1][1], af[1][2], af[1][3], aBase + 16 * TSTRIDE + k16 * 32);
                uint32_t bf[4][4];
#pragma unroll
                for (int nb = 0; nb < 4; nb++)
                    ldm_x4(bf[nb][0], bf[nb][1], bf[nb][2], bf[nb][3],
                           bBase + nb * 16 * TSTRIDE + k16 * 32);
#pragma unroll
                for (int mt = 0; mt < 2; mt++)
#pragma unroll
                    for (int nb = 0; nb < 4; nb++) {
                        mma_bf16(acc[mt][nb * 2][0], acc[mt][nb * 2][1],
                                 acc[mt][nb * 2][2], acc[mt][nb * 2][3],
                                 af[mt][0], af[mt][1], af[mt][2], af[mt][3],
                                 bf[nb][0], bf[nb][1]);
                        mma_bf16(acc[mt][nb * 2 + 1][0], acc[mt][nb * 2 + 1][1],
                                 acc[mt][nb * 2 + 1][2], acc[mt][nb * 2 + 1][3],
                                 af[mt][0], af[mt][1], af[mt][2], af[mt][3],
                                 bf[nb][2], bf[nb][3]);
                    }
            }
        }

        // ---- epilogue: Q fp32; K/V fp16 interleaved chunks ----
        const float* bias = (m == 0) ? bQ : (m == 1) ? bK : bV;
        char* kvb = reinterpret_cast<char*>(g_KVh);
#pragma unroll
        for (int nt = 0; nt < 8; nt++) {
            int col = wn * 64 + nt * 8 + (lane & 3) * 2;
            float b0 = bias[col], b1 = bias[col + 1];
#pragma unroll
            for (int mt = 0; mt < 2; mt++) {
                int row = t * 128 + wm * 32 + mt * 16 + (lane >> 2);
#pragma unroll
                for (int half = 0; half < 2; half++) {
                    int rr = row + half * 8;
                    if (rr >= N) continue;
                    float v0 = acc[mt][nt][2 * half] + b0;
                    float v1 = acc[mt][nt][2 * half + 1] + b1;
                    if (m == 0) {
                        *reinterpret_cast<float2*>(g_Q + (size_t)rr * 128 + col) =
                            make_float2(v0, v1);
                    } else {
                        __half2* o = reinterpret_cast<__half2*>(
                            kvb + (size_t)rr * 512 + (col >> 2) * 16 +
                            (m == 2 ? 8 : 0) + (col & 3) * 2);
                        *o = __floats2half2_rn(v0, v1);
                    }
                }
            }
        }
        __syncthreads();
    }
}

// ============================================================
// CSR construction: hist (atomic, stores rank) -> scan ->
// scatter (NO atomics: pos = row[dst] + rank)
// ============================================================
__global__ void hist_k(const int* __restrict__ dst, int E) {
    int i = blockIdx.x * 256 + threadIdx.x;
    int base = i * 8;
    if (base + 7 < E) {
        int4 d0 = *reinterpret_cast<const int4*>(dst + base);
        int4 d1 = *reinterpret_cast<const int4*>(dst + base + 4);
        int r0 = atomicAdd(&g_cnt[d0.x], 1);
        int r1 = atomicAdd(&g_cnt[d0.y], 1);
        int r2 = atomicAdd(&g_cnt[d0.z], 1);
        int r3 = atomicAdd(&g_cnt[d0.w], 1);
        int r4 = atomicAdd(&g_cnt[d1.x], 1);
        int r5 = atomicAdd(&g_cnt[d1.y], 1);
        int r6 = atomicAdd(&g_cnt[d1.z], 1);
        int r7 = atomicAdd(&g_cnt[d1.w], 1);
        *reinterpret_cast<int4*>(g_rank + base)     = make_int4(r0, r1, r2, r3);
        *reinterpret_cast<int4*>(g_rank + base + 4) = make_int4(r4, r5, r6, r7);
    } else {
        for (int j = base; j < E; j++) g_rank[j] = atomicAdd(&g_cnt[dst[j]], 1);
    }
}

__device__ __forceinline__ int warp_incl_scan(int v, int lane) {
#pragma unroll
    for (int off = 1; off < 32; off <<= 1) {
        int t = __shfl_up_sync(0xffffffffu, v, off);
        if (lane >= off) v += t;
    }
    return v;
}

// block-local exclusive scan; also re-zeroes g_cnt for the next replay
__global__ void scan_partial(int N) {
    __shared__ int wsum[32];
    int tid = threadIdx.x, lane = tid & 31, wid = tid >> 5;
    int idx = blockIdx.x * 1024 + tid;
    int x = 0;
    if (idx < N) {
        x = g_cnt[idx];
        g_cnt[idx] = 0;
    }
    int v = warp_incl_scan(x, lane);
    if (lane == 31) wsum[wid] = v;
    __syncthreads();
    if (wid == 0) wsum[lane] = warp_incl_scan(wsum[lane], lane);
    __syncthreads();
    int incl = v + (wid > 0 ? wsum[wid - 1] : 0);
    if (idx < N) g_row[idx] = incl - x;
    if (tid == 1023) g_bsum[blockIdx.x] = incl;
}

__global__ void scan_add(int N, int E) {
    __shared__ int boff;
    int b = blockIdx.x, tid = threadIdx.x;
    if (tid < 32) {
        int acc = 0;
        for (int i = tid; i < b; i += 32) acc += g_bsum[i];
#pragma unroll
        for (int o = 16; o; o >>= 1) acc += __shfl_xor_sync(0xffffffffu, acc, o);
        if (tid == 0) boff = acc;
    }
    __syncthreads();
    int idx = b * 1024 + tid;
    if (idx < N) g_row[idx] += boff;
    if (idx == 0) g_row[N] = E;
}

// atomic-free scatter: pos = row[dst] + rank (unique by construction)
__global__ void scatter_k(const int* __restrict__ src, const int* __restrict__ dst, int E) {
    int i = blockIdx.x * 256 + threadIdx.x;
    int base = i * 8;
    if (base + 7 < E) {
        int4 s0 = *reinterpret_cast<const int4*>(src + base);
        int4 s1 = *reinterpret_cast<const int4*>(src + base + 4);
        int4 d0 = *reinterpret_cast<const int4*>(dst + base);
        int4 d1 = *reinterpret_cast<const int4*>(dst + base + 4);
        int4 r0 = *reinterpret_cast<const int4*>(g_rank + base);
        int4 r1 = *reinterpret_cast<const int4*>(g_rank + base + 4);
        g_srcs[g_row[d0.x] + r0.x] = s0.x;
        g_srcs[g_row[d0.y] + r0.y] = s0.y;
        g_srcs[g_row[d0.z] + r0.z] = s0.z;
        g_srcs[g_row[d0.w] + r0.w] = s0.w;
        g_srcs[g_row[d1.x] + r1.x] = s1.x;
        g_srcs[g_row[d1.y] + r1.y] = s1.y;
        g_srcs[g_row[d1.z] + r1.z] = s1.z;
        g_srcs[g_row[d1.w] + r1.w] = s1.w;
    } else {
        for (int j = base; j < E; j++)
            g_srcs[g_row[dst[j]] + g_rank[j]] = src[j];
    }
}

// ============================================================
// Gather attention: one warp per dst node, interleaved fp16 KV,
// 4-edge unroll (R6 form — proven best across R8/R14 A/Bs).
// ============================================================
__global__ void gather_attn(float* __restrict__ out, int N) {
    int w = (blockIdx.x * blockDim.x + threadIdx.x) >> 5;
    int lane = threadIdx.x & 31;
    if (w >= N) return;

    const float4 q = reinterpret_cast<const float4*>(g_Q)[(size_t)w * 32 + lane];
    int beg = g_row[w], end = g_row[w + 1];

    float ax = 0.f, ay = 0.f, az = 0.f, aw = 0.f, z = 0.f;
    const uint4* KV = reinterpret_cast<const uint4*>(g_KVh);

    int i = beg;
    for (; i + 3 < end; i += 4) {
        int ss[4];
#pragma unroll
        for (int j = 0; j < 4; j++) ss[j] = g_srcs[i + j];
        uint4 kv[4];
#pragma unroll
        for (int j = 0; j < 4; j++) kv[j] = KV[(size_t)ss[j] * 32 + lane];
        float ee[4];
#pragma unroll
        for (int j = 0; j < 4; j++) {
            float2 ka = __half22float2(*reinterpret_cast<__half2*>(&kv[j].x));
            float2 kb = __half22float2(*reinterpret_cast<__half2*>(&kv[j].y));
            float d = ka.x * q.x + ka.y * q.y + kb.x * q.z + kb.y * q.w;
            d += __shfl_xor_sync(0xffffffffu, d, 1);
            d += __shfl_xor_sync(0xffffffffu, d, 2);
            ee[j] = __expf(fminf(5.f, fmaxf(-5.f, d * 0.25f)));
        }
#pragma unroll
        for (int j = 0; j < 4; j++) {
            float2 va = __half22float2(*reinterpret_cast<__half2*>(&kv[j].z));
            float2 vb = __half22float2(*reinterpret_cast<__half2*>(&kv[j].w));
            z  += ee[j];
            ax += va.x * ee[j];
            ay += va.y * ee[j];
            az += vb.x * ee[j];
            aw += vb.y * ee[j];
        }
    }
    for (; i < end; i++) {
        uint4 kv = KV[(size_t)g_srcs[i] * 32 + lane];
        float2 ka = __half22float2(*reinterpret_cast<__half2*>(&kv.x));
        float2 kb = __half22float2(*reinterpret_cast<__half2*>(&kv.y));
        float d = ka.x * q.x + ka.y * q.y + kb.x * q.z + kb.y * q.w;
        d += __shfl_xor_sync(0xffffffffu, d, 1);
        d += __shfl_xor_sync(0xffffffffu, d, 2);
        float e = __expf(fminf(5.f, fmaxf(-5.f, d * 0.25f)));
        float2 va = __half22float2(*reinterpret_cast<__half2*>(&kv.z));
        float2 vb = __half22float2(*reinterpret_cast<__half2*>(&kv.w));
        z  += e;
        ax += va.x * e;
        ay += va.y * e;
        az += vb.x * e;
        aw += vb.y * e;
    }

    float inv = (z > 0.f) ? 1.f / z : 0.f;
    reinterpret_cast<float4*>(out)[(size_t)w * 32 + lane] =
        make_float4(ax * inv, ay * inv, az * inv, aw * inv);
}

// ============================================================
extern "C" void kernel_launch(void* const* d_in, const int* in_sizes, int n_in,
                              void* d_out, int out_size) {
    const float* h  = (const float*)d_in[0];
    const int*   src = (const int*)d_in[1];
    const int*   dst = (const int*)d_in[2];
    const float* WQ = (const float*)d_in[3];
    const float* bQ = (const float*)d_in[4];
    const float* WK = (const float*)d_in[5];
    const float* bK = (const float*)d_in[6];
    const float* WV = (const float*)d_in[7];
    const float* bV = (const float*)d_in[8];
    int N = in_sizes[0] / INDIM;
    int E = in_sizes[1];
    int NT = (N + 127) / 128;

    cudaFuncSetAttribute(qkv_hmma, cudaFuncAttributeMaxDynamicSharedMemorySize, SM_TOTAL);

    cudaStream_t s2;
    cudaStreamCreateWithFlags(&s2, cudaStreamNonBlocking);
    cudaEvent_t evF, evJ;
    cudaEventCreateWithFlags(&evF, cudaEventDisableTiming);
    cudaEventCreateWithFlags(&evJ, cudaEventDisableTiming);

    cudaEventRecord(evF, 0);
    cudaStreamWaitEvent(s2, evF, 0);

    // --- s2: CSR chain (4 kernels, scatter atomic-free) ---
    int E8 = (E + 7) / 8;
    int nb = (N + 1023) / 1024;
    hist_k<<<(E8 + 255) / 256, 256, 0, s2>>>(dst, E);
    scan_partial<<<nb, 1024, 0, s2>>>(N);
    scan_add<<<nb, 1024, 0, s2>>>(N, E);
    scatter_k<<<(E8 + 255) / 256, 256, 0, s2>>>(src, dst, E);
    cudaEventRecord(evJ, s2);

    // --- default stream: QKV chain ---
    conv_W<<<48, 256>>>(WQ, WK, WV);
    qkv_hmma<<<NT, 256, SM_TOTAL>>>(h, bQ, bK, bV, N);

    cudaStreamWaitEvent(0, evJ, 0);
    gather_attn<<<(N + 7) / 8, 256>>>((float*)d_out, N);
}